// round 6
// baseline (speedup 1.0000x reference)
#include <cuda_runtime.h>
#include <cuda_fp16.h>
#include <cstdint>

// ---------------------------------------------------------------------------
// Problem constants
// ---------------------------------------------------------------------------
#define B_ 4
#define T_ 160
#define U_ 80
#define DE 640
#define HH 640
#define VV 1024
#define TU (T_ * U_)          // 12800
#define MTOT (B_ * TU)        // 51200

// Joint GEMM tiling
#define BM 128
#define BN 128
#define BK 64
#define KITERS (HH / BK)      // 10
#define STAGES 3

// ---------------------------------------------------------------------------
// Device scratch
// ---------------------------------------------------------------------------
__device__ float g_proj_e[B_ * T_ * HH];
__device__ float g_proj_d[B_ * U_ * HH];
__device__ __align__(16) __half g_A[(size_t)MTOT * HH];   // fp16(tanh(...))
__device__ __align__(16) __half g_B[VV * HH];             // W2^T fp16, [n][k]

// ---------------------------------------------------------------------------
// Helpers
// ---------------------------------------------------------------------------
__device__ __forceinline__ uint32_t smem_u32(const void* p) {
    uint32_t a;
    asm("{ .reg .u64 t; cvta.to.shared.u64 t, %1; cvt.u32.u64 %0, t; }"
        : "=r"(a) : "l"(p));
    return a;
}

__device__ __forceinline__ float fast_tanh(float x) {
    float e;
    asm("ex2.approx.f32 %0, %1;" : "=f"(e) : "f"(x * 2.885390081777927f));
    float r;
    asm("rcp.approx.f32 %0, %1;" : "=f"(r) : "f"(e + 1.0f));
    return fmaf(-2.0f, r, 1.0f);
}

#define CP_ASYNC16(saddr, gptr) \
    asm volatile("cp.async.cg.shared.global [%0], [%1], 16;" \
                 :: "r"(saddr), "l"(gptr))
#define CP_COMMIT()  asm volatile("cp.async.commit_group;" ::: "memory")
#define CP_WAIT1()   asm volatile("cp.async.wait_group 1;" ::: "memory")
#define CP_WAIT0()   asm volatile("cp.async.wait_group 0;" ::: "memory")

#define LDSM4(r0, r1, r2, r3, a) \
    asm volatile("ldmatrix.sync.aligned.m8n8.x4.shared.b16 {%0,%1,%2,%3}, [%4];" \
                 : "=r"(r0), "=r"(r1), "=r"(r2), "=r"(r3) : "r"(a))

#define MMA16816(d, a, b0, b1) \
    asm volatile("mma.sync.aligned.m16n8k16.row.col.f32.f16.f16.f32 " \
                 "{%0,%1,%2,%3}, {%4,%5,%6,%7}, {%8,%9}, {%0,%1,%2,%3};" \
                 : "+f"((d)[0]), "+f"((d)[1]), "+f"((d)[2]), "+f"((d)[3]) \
                 : "r"((a)[0]), "r"((a)[1]), "r"((a)[2]), "r"((a)[3]), \
                   "r"(b0), "r"(b1))

// ---------------------------------------------------------------------------
// Stage 1: both projections, one launch, register-prefetch double buffering
// ---------------------------------------------------------------------------
__global__ void proj_both(const float* __restrict__ enc,
                          const float* __restrict__ dec,
                          const float* __restrict__ W1,
                          const float* __restrict__ b1,
                          float* __restrict__ pe,
                          float* __restrict__ pd)
{
    __shared__ float As[16][65];
    __shared__ float Bs[16][64];

    const int ltid = threadIdx.x;
    const bool is_dec = (blockIdx.y >= 10);
    const int m0 = (is_dec ? (blockIdx.y - 10) : blockIdx.y) * 64;
    const int n0 = blockIdx.x * 64;

    const float* __restrict__ A    = is_dec ? dec : enc;
    const float* __restrict__ W    = is_dec ? (W1 + (size_t)DE * HH) : W1;
    const float* __restrict__ bias = is_dec ? b1 : nullptr;
    float* __restrict__ C          = is_dec ? pd : pe;

    const int arow = ltid >> 2;
    const int ak4  = (ltid & 3) * 4;
    const int bk   = ltid >> 4;
    const int bn   = (ltid & 15) * 4;
    const int tx = ltid & 15;
    const int ty = ltid >> 4;

    float acc[4][4] = {};

    float4 av = *(const float4*)&A[(size_t)(m0 + arow) * DE + ak4];
    float4 bv = *(const float4*)&W[(size_t)bk * HH + n0 + bn];

    for (int k0 = 0; k0 < DE; k0 += 16) {
        As[ak4 + 0][arow] = av.x;
        As[ak4 + 1][arow] = av.y;
        As[ak4 + 2][arow] = av.z;
        As[ak4 + 3][arow] = av.w;
        *(float4*)&Bs[bk][bn] = bv;
        __syncthreads();

        if (k0 + 16 < DE) {
            av = *(const float4*)&A[(size_t)(m0 + arow) * DE + k0 + 16 + ak4];
            bv = *(const float4*)&W[(size_t)(k0 + 16 + bk) * HH + n0 + bn];
        }

        #pragma unroll
        for (int k = 0; k < 16; k++) {
            float a[4], b[4];
            #pragma unroll
            for (int j = 0; j < 4; j++) a[j] = As[k][ty * 4 + j];
            #pragma unroll
            for (int i = 0; i < 4; i++) b[i] = Bs[k][tx * 4 + i];
            #pragma unroll
            for (int j = 0; j < 4; j++)
                #pragma unroll
                for (int i = 0; i < 4; i++)
                    acc[j][i] = fmaf(a[j], b[i], acc[j][i]);
        }
        __syncthreads();
    }

    #pragma unroll
    for (int j = 0; j < 4; j++) {
        const int row = m0 + ty * 4 + j;
        #pragma unroll
        for (int i = 0; i < 4; i++) {
            float v = acc[j][i];
            if (bias) v += bias[n0 + tx * 4 + i];
            C[(size_t)row * HH + n0 + tx * 4 + i] = v;
        }
    }
}

// ---------------------------------------------------------------------------
// Stage 1.5a: W2 transpose -> fp16, tiled through smem
// ---------------------------------------------------------------------------
__global__ void prep_w2(const float* __restrict__ W2, __half* __restrict__ B)
{
    __shared__ float tile[32][33];
    const int n0 = blockIdx.x * 32;
    const int k0 = blockIdx.y * 32;
    const int x = threadIdx.x & 31;
    const int y = threadIdx.x >> 5;

    #pragma unroll
    for (int j = 0; j < 4; j++)
        tile[y + j * 8][x] = W2[(size_t)(k0 + y + j * 8) * VV + n0 + x];
    __syncthreads();

    #pragma unroll
    for (int j = 0; j < 4; j++) {
        int ny = y + j * 8;
        B[(size_t)(n0 + ny) * HH + k0 + x] = __float2half_rn(tile[x][ny]);
    }
}

// ---------------------------------------------------------------------------
// Stage 1.5b: A = fp16(tanh(pe + pd))
// ---------------------------------------------------------------------------
__global__ void prep_a(__half* __restrict__ A)
{
    int idx = blockIdx.x * 256 + threadIdx.x;
    int row = idx / 160;
    int q = idx - row * 160;
    int b = row / TU;
    int rem = row - b * TU;
    int t = rem / U_;
    int u = rem - t * U_;

    const float4 e = *(const float4*)&g_proj_e[(size_t)(b * T_ + t) * HH + q * 4];
    const float4 d = *(const float4*)&g_proj_d[(size_t)(b * U_ + u) * HH + q * 4];

    __half h[4];
    h[0] = __float2half_rn(fast_tanh(e.x + d.x));
    h[1] = __float2half_rn(fast_tanh(e.y + d.y));
    h[2] = __float2half_rn(fast_tanh(e.z + d.z));
    h[3] = __float2half_rn(fast_tanh(e.w + d.w));
    *(uint2*)&A[(size_t)row * HH + q * 4] = *(uint2*)h;
}

// ---------------------------------------------------------------------------
// Stage 2: HMMA joint GEMM. out[51200,1024] = A@B^T + b2.
// BM=128, BN=128, BK=64; 128 threads = 4 warps (2M x 2N), warp tile 64x64.
// LDSM bytes/MMA: 128 (vs 192 at 64x32) -> crossbar 1.25 cyc/MMA vs tensor 1.
// 3-stage cp.async pipeline, one sync/iter, 2 CTAs/SM (96KB smem each).
// ---------------------------------------------------------------------------
#define STG_STRIDE 32768u
#define SMEM_TOTAL (STAGES * 32768)

__device__ __forceinline__ void load_buf(uint32_t sbuf,
                                         const __half* __restrict__ A,
                                         const __half* __restrict__ B,
                                         int m0, int n0, int k0)
{
    const int tid = threadIdx.x;
    // A tile: 128 rows x 64 halfs = 1024 16B-chunks, 8 per thread
    #pragma unroll
    for (int i = 0; i < 8; i++) {
        int ci = tid + i * 128;
        int row = ci >> 3;
        int ck = ci & 7;
        uint32_t so = sbuf + row * 128 + ((ck ^ (row & 7)) << 4);
        CP_ASYNC16(so, A + (size_t)(m0 + row) * HH + k0 + ck * 8);
    }
    // B tile: 128 rows x 64 halfs = 1024 chunks, 8 per thread
    #pragma unroll
    for (int i = 0; i < 8; i++) {
        int ci = tid + i * 128;
        int row = ci >> 3;
        int ck = ci & 7;
        uint32_t so = sbuf + 16384u + row * 128 + ((ck ^ (row & 7)) << 4);
        CP_ASYNC16(so, B + (size_t)(n0 + row) * HH + k0 + ck * 8);
    }
}

__global__ void __launch_bounds__(128, 2)
joint_gemm(const __half* __restrict__ A,
           const __half* __restrict__ B,
           const float* __restrict__ b2,
           float* __restrict__ out)
{
    extern __shared__ __align__(1024) char smem[];
    const uint32_t sb = smem_u32(smem);

    const int tid  = threadIdx.x;
    const int lane = tid & 31;
    const int wid  = tid >> 5;
    const int wm   = wid & 1;          // 0..1 -> 64-row stripes
    const int wn   = wid >> 1;         // 0..1 -> 64-col stripes
    const int n0   = blockIdx.x * BN;
    const int m0   = blockIdx.y * BM;

    const int lml = lane & 15;
    const int lmh = lane >> 4;

    float acc[4][8][4];
    #pragma unroll
    for (int a = 0; a < 4; a++)
        #pragma unroll
        for (int n = 0; n < 8; n++)
            #pragma unroll
            for (int i = 0; i < 4; i++) acc[a][n][i] = 0.0f;

    load_buf(sb,              A, B, m0, n0, 0);
    CP_COMMIT();
    load_buf(sb + STG_STRIDE, A, B, m0, n0, BK);
    CP_COMMIT();
    CP_WAIT1();
    __syncthreads();

    for (int c = 0; c < KITERS; c++) {
        const uint32_t sbuf = sb + (uint32_t)(c % STAGES) * STG_STRIDE;

        if (c + 2 < KITERS) {
            load_buf(sb + (uint32_t)((c + 2) % STAGES) * STG_STRIDE,
                     A, B, m0, n0, (c + 2) * BK);
            CP_COMMIT();
        }

        #pragma unroll
        for (int ks = 0; ks < 4; ks++) {
            const int ck = 2 * ks + lmh;

            // A fragments: 4 m-atoms (64 rows)
            uint32_t af[4][4];
            #pragma unroll
            for (int a = 0; a < 4; a++) {
                uint32_t row = (uint32_t)(wm * 64 + a * 16 + lml);
                LDSM4(af[a][0], af[a][1], af[a][2], af[a][3],
                      sbuf + row * 128 + (uint32_t)((ck ^ (row & 7)) << 4));
            }
            // B fragments: 4 n16-groups (64 cols)
            uint32_t bf[4][4];
            #pragma unroll
            for (int p = 0; p < 4; p++) {
                uint32_t row = (uint32_t)(wn * 64 + p * 16 + lml);
                LDSM4(bf[p][0], bf[p][1], bf[p][2], bf[p][3],
                      sbuf + 16384u + row * 128 +
                      (uint32_t)((ck ^ (row & 7)) << 4));
            }
            // 32 MMAs: 4 m-atoms x 8 n-atoms
            #pragma unroll
            for (int a = 0; a < 4; a++)
                #pragma unroll
                for (int n = 0; n < 8; n++) {
                    int p = n >> 1, s = n & 1;
                    MMA16816(acc[a][n], af[a], bf[p][s], bf[p][s + 2]);
                }
        }

        if (c + 2 < KITERS) CP_WAIT1();
        else                CP_WAIT0();
        __syncthreads();
    }

    // epilogue: +b2, direct stores
    #pragma unroll
    for (int n = 0; n < 8; n++) {
        const int col = n0 + wn * 64 + n * 8 + (lane & 3) * 2;
        const float2 bb = *(const float2*)&b2[col];
        #pragma unroll
        for (int a = 0; a < 4; a++) {
            const size_t r0 = (size_t)m0 + wm * 64 + a * 16 + (lane >> 2);
            float2 o0 = { acc[a][n][0] + bb.x, acc[a][n][1] + bb.y };
            float2 o1 = { acc[a][n][2] + bb.x, acc[a][n][3] + bb.y };
            *(float2*)&out[r0 * VV + col]       = o0;
            *(float2*)&out[(r0 + 8) * VV + col] = o1;
        }
    }
}

// ---------------------------------------------------------------------------
// Launch
// ---------------------------------------------------------------------------
extern "C" void kernel_launch(void* const* d_in, const int* in_sizes, int n_in,
                              void* d_out, int out_size)
{
    const float* enc = (const float*)d_in[0];
    const float* dec = (const float*)d_in[1];
    const float* W1  = (const float*)d_in[2];
    const float* b1  = (const float*)d_in[3];
    const float* W2  = (const float*)d_in[4];
    const float* b2  = (const float*)d_in[5];
    float* out = (float*)d_out;

    float *pe = nullptr, *pd = nullptr;
    __half *ga = nullptr, *gb = nullptr;
    cudaGetSymbolAddress((void**)&pe, g_proj_e);
    cudaGetSymbolAddress((void**)&pd, g_proj_d);
    cudaGetSymbolAddress((void**)&ga, g_A);
    cudaGetSymbolAddress((void**)&gb, g_B);

    cudaFuncSetAttribute(joint_gemm,
                         cudaFuncAttributeMaxDynamicSharedMemorySize, SMEM_TOTAL);

    proj_both<<<dim3(HH / 64, 15), 256>>>(enc, dec, W1, b1, pe, pd);
    prep_w2<<<dim3(VV / 32, HH / 32), 256>>>(W2, gb);
    prep_a<<<(MTOT * 160) / 256, 256>>>(ga);

    joint_gemm<<<dim3(VV / BN, MTOT / BM), 128, SMEM_TOTAL>>>(ga, gb, b2, out);
}

// round 7
// speedup vs baseline: 1.0519x; 1.0519x over previous
#include <cuda_runtime.h>
#include <cuda_fp16.h>
#include <cstdint>

// ---------------------------------------------------------------------------
// Problem constants
// ---------------------------------------------------------------------------
#define B_ 4
#define T_ 160
#define U_ 80
#define DE 640
#define HH 640
#define VV 1024
#define TU (T_ * U_)          // 12800
#define MTOT (B_ * TU)        // 51200

// Joint GEMM tiling
#define BM 128
#define BN 128
#define BK 64
#define KITERS (HH / BK)      // 10
#define STAGES 3

// ---------------------------------------------------------------------------
// Device scratch
// ---------------------------------------------------------------------------
__device__ float g_proj_e[B_ * T_ * HH];
__device__ float g_proj_d[B_ * U_ * HH];
__device__ __align__(16) __half g_A[(size_t)MTOT * HH];   // fp16(tanh(...))
__device__ __align__(16) __half g_B[VV * HH];             // W2^T fp16, [n][k]

// ---------------------------------------------------------------------------
// Helpers
// ---------------------------------------------------------------------------
__device__ __forceinline__ uint32_t smem_u32(const void* p) {
    uint32_t a;
    asm("{ .reg .u64 t; cvta.to.shared.u64 t, %1; cvt.u32.u64 %0, t; }"
        : "=r"(a) : "l"(p));
    return a;
}

__device__ __forceinline__ float fast_tanh(float x) {
    float e;
    asm("ex2.approx.f32 %0, %1;" : "=f"(e) : "f"(x * 2.885390081777927f));
    float r;
    asm("rcp.approx.f32 %0, %1;" : "=f"(r) : "f"(e + 1.0f));
    return fmaf(-2.0f, r, 1.0f);
}

#define CP_ASYNC16(saddr, gptr) \
    asm volatile("cp.async.cg.shared.global [%0], [%1], 16;" \
                 :: "r"(saddr), "l"(gptr))
#define CP_COMMIT()  asm volatile("cp.async.commit_group;" ::: "memory")
#define CP_WAIT1()   asm volatile("cp.async.wait_group 1;" ::: "memory")
#define CP_WAIT0()   asm volatile("cp.async.wait_group 0;" ::: "memory")

#define LDSM4(r0, r1, r2, r3, a) \
    asm volatile("ldmatrix.sync.aligned.m8n8.x4.shared.b16 {%0,%1,%2,%3}, [%4];" \
                 : "=r"(r0), "=r"(r1), "=r"(r2), "=r"(r3) : "r"(a))

#define MMA16816(d, a, b0, b1) \
    asm volatile("mma.sync.aligned.m16n8k16.row.col.f32.f16.f16.f32 " \
                 "{%0,%1,%2,%3}, {%4,%5,%6,%7}, {%8,%9}, {%0,%1,%2,%3};" \
                 : "+f"((d)[0]), "+f"((d)[1]), "+f"((d)[2]), "+f"((d)[3]) \
                 : "r"((a)[0]), "r"((a)[1]), "r"((a)[2]), "r"((a)[3]), \
                   "r"(b0), "r"(b1))

// ---------------------------------------------------------------------------
// Stage 1: both projections. BM=64, BN=32, BK=16, 128 threads.
// grid = (20, 15): y 0..9 = enc (m 0..639), y 10..14 = dec (m 0..319)
// 300 CTAs -> 2+ CTAs/SM, register-prefetch double buffering.
// ---------------------------------------------------------------------------
__global__ void __launch_bounds__(128)
proj_both(const float* __restrict__ enc,
          const float* __restrict__ dec,
          const float* __restrict__ W1,
          const float* __restrict__ b1,
          float* __restrict__ pe,
          float* __restrict__ pd)
{
    __shared__ float As[16][65];
    __shared__ float Bs[16][32];

    const int ltid = threadIdx.x;
    const bool is_dec = (blockIdx.y >= 10);
    const int m0 = (is_dec ? (blockIdx.y - 10) : blockIdx.y) * 64;
    const int n0 = blockIdx.x * 32;

    const float* __restrict__ A    = is_dec ? dec : enc;
    const float* __restrict__ W    = is_dec ? (W1 + (size_t)DE * HH) : W1;
    const float* __restrict__ bias = is_dec ? b1 : nullptr;
    float* __restrict__ C          = is_dec ? pd : pe;

    // A loader: 64 rows x 16 cols = 256 float4, 2 per thread
    const int ar0 = ltid >> 1;            // via ci = ltid + i*128
    const int bk  = ltid >> 3;            // 0..15
    const int bn  = (ltid & 7) * 4;       // 0..28
    const int tx  = ltid & 7;             // 8 col groups x 4
    const int ty  = ltid >> 3;            // 16 row groups x 4
    (void)ar0;

    float acc[4][4] = {};

    // prefetch k0 = 0
    float4 av[2], bv;
    #pragma unroll
    for (int i = 0; i < 2; i++) {
        int ci = ltid + i * 128;
        av[i] = *(const float4*)&A[(size_t)(m0 + (ci >> 2)) * DE + (ci & 3) * 4];
    }
    bv = *(const float4*)&W[(size_t)bk * HH + n0 + bn];

    for (int k0 = 0; k0 < DE; k0 += 16) {
        #pragma unroll
        for (int i = 0; i < 2; i++) {
            int ci = ltid + i * 128;
            int arow = ci >> 2;
            int ak4  = (ci & 3) * 4;
            As[ak4 + 0][arow] = av[i].x;
            As[ak4 + 1][arow] = av[i].y;
            As[ak4 + 2][arow] = av[i].z;
            As[ak4 + 3][arow] = av[i].w;
        }
        *(float4*)&Bs[bk][bn] = bv;
        __syncthreads();

        if (k0 + 16 < DE) {
            #pragma unroll
            for (int i = 0; i < 2; i++) {
                int ci = ltid + i * 128;
                av[i] = *(const float4*)&A[(size_t)(m0 + (ci >> 2)) * DE +
                                           k0 + 16 + (ci & 3) * 4];
            }
            bv = *(const float4*)&W[(size_t)(k0 + 16 + bk) * HH + n0 + bn];
        }

        #pragma unroll
        for (int k = 0; k < 16; k++) {
            float a[4], b[4];
            #pragma unroll
            for (int j = 0; j < 4; j++) a[j] = As[k][ty * 4 + j];
            #pragma unroll
            for (int i = 0; i < 4; i++) b[i] = Bs[k][tx * 4 + i];
            #pragma unroll
            for (int j = 0; j < 4; j++)
                #pragma unroll
                for (int i = 0; i < 4; i++)
                    acc[j][i] = fmaf(a[j], b[i], acc[j][i]);
        }
        __syncthreads();
    }

    #pragma unroll
    for (int j = 0; j < 4; j++) {
        const int row = m0 + ty * 4 + j;
        #pragma unroll
        for (int i = 0; i < 4; i++) {
            float v = acc[j][i];
            if (bias) v += bias[n0 + tx * 4 + i];
            C[(size_t)row * HH + n0 + tx * 4 + i] = v;
        }
    }
}

// ---------------------------------------------------------------------------
// Stage 1.5a: W2 transpose -> fp16, tiled through smem
// ---------------------------------------------------------------------------
__global__ void prep_w2(const float* __restrict__ W2, __half* __restrict__ B)
{
    __shared__ float tile[32][33];
    const int n0 = blockIdx.x * 32;
    const int k0 = blockIdx.y * 32;
    const int x = threadIdx.x & 31;
    const int y = threadIdx.x >> 5;

    #pragma unroll
    for (int j = 0; j < 4; j++)
        tile[y + j * 8][x] = W2[(size_t)(k0 + y + j * 8) * VV + n0 + x];
    __syncthreads();

    #pragma unroll
    for (int j = 0; j < 4; j++) {
        int ny = y + j * 8;
        B[(size_t)(n0 + ny) * HH + k0 + x] = __float2half_rn(tile[x][ny]);
    }
}

// ---------------------------------------------------------------------------
// Stage 1.5b: A = fp16(tanh(pe + pd)); grid (U, T, B), 160 thr, NO div/mod
// ---------------------------------------------------------------------------
__global__ void __launch_bounds__(160)
prep_a(__half* __restrict__ A)
{
    const int u = blockIdx.x;
    const int t = blockIdx.y;
    const int b = blockIdx.z;
    const int q4 = threadIdx.x * 4;       // 0..636

    const float4 e = *(const float4*)&g_proj_e[(size_t)(b * T_ + t) * HH + q4];
    const float4 d = *(const float4*)&g_proj_d[(size_t)(b * U_ + u) * HH + q4];

    __half h[4];
    h[0] = __float2half_rn(fast_tanh(e.x + d.x));
    h[1] = __float2half_rn(fast_tanh(e.y + d.y));
    h[2] = __float2half_rn(fast_tanh(e.z + d.z));
    h[3] = __float2half_rn(fast_tanh(e.w + d.w));

    const size_t row = (size_t)b * TU + t * U_ + u;
    *(uint2*)&A[row * HH + q4] = *(uint2*)h;
}

// ---------------------------------------------------------------------------
// Stage 2: HMMA joint GEMM (unchanged from best measured variant).
// BM=128, BN=128, BK=64; 128 threads = 4 warps (2M x 2N), warp tile 64x64.
// 3-stage cp.async pipeline, one sync/iter, 2 CTAs/SM.
// ---------------------------------------------------------------------------
#define STG_STRIDE 32768u
#define SMEM_TOTAL (STAGES * 32768)

__device__ __forceinline__ void load_buf(uint32_t sbuf,
                                         const __half* __restrict__ A,
                                         const __half* __restrict__ B,
                                         int m0, int n0, int k0)
{
    const int tid = threadIdx.x;
    #pragma unroll
    for (int i = 0; i < 8; i++) {
        int ci = tid + i * 128;
        int row = ci >> 3;
        int ck = ci & 7;
        uint32_t so = sbuf + row * 128 + ((ck ^ (row & 7)) << 4);
        CP_ASYNC16(so, A + (size_t)(m0 + row) * HH + k0 + ck * 8);
    }
    #pragma unroll
    for (int i = 0; i < 8; i++) {
        int ci = tid + i * 128;
        int row = ci >> 3;
        int ck = ci & 7;
        uint32_t so = sbuf + 16384u + row * 128 + ((ck ^ (row & 7)) << 4);
        CP_ASYNC16(so, B + (size_t)(n0 + row) * HH + k0 + ck * 8);
    }
}

__global__ void __launch_bounds__(128, 2)
joint_gemm(const __half* __restrict__ A,
           const __half* __restrict__ B,
           const float* __restrict__ b2,
           float* __restrict__ out)
{
    extern __shared__ __align__(1024) char smem[];
    const uint32_t sb = smem_u32(smem);

    const int tid  = threadIdx.x;
    const int lane = tid & 31;
    const int wid  = tid >> 5;
    const int wm   = wid & 1;
    const int wn   = wid >> 1;
    const int n0   = blockIdx.x * BN;
    const int m0   = blockIdx.y * BM;

    const int lml = lane & 15;
    const int lmh = lane >> 4;

    float acc[4][8][4];
    #pragma unroll
    for (int a = 0; a < 4; a++)
        #pragma unroll
        for (int n = 0; n < 8; n++)
            #pragma unroll
            for (int i = 0; i < 4; i++) acc[a][n][i] = 0.0f;

    load_buf(sb,              A, B, m0, n0, 0);
    CP_COMMIT();
    load_buf(sb + STG_STRIDE, A, B, m0, n0, BK);
    CP_COMMIT();
    CP_WAIT1();
    __syncthreads();

    for (int c = 0; c < KITERS; c++) {
        const uint32_t sbuf = sb + (uint32_t)(c % STAGES) * STG_STRIDE;

        if (c + 2 < KITERS) {
            load_buf(sb + (uint32_t)((c + 2) % STAGES) * STG_STRIDE,
                     A, B, m0, n0, (c + 2) * BK);
            CP_COMMIT();
        }

        #pragma unroll
        for (int ks = 0; ks < 4; ks++) {
            const int ck = 2 * ks + lmh;

            uint32_t af[4][4];
            #pragma unroll
            for (int a = 0; a < 4; a++) {
                uint32_t row = (uint32_t)(wm * 64 + a * 16 + lml);
                LDSM4(af[a][0], af[a][1], af[a][2], af[a][3],
                      sbuf + row * 128 + (uint32_t)((ck ^ (row & 7)) << 4));
            }
            uint32_t bf[4][4];
            #pragma unroll
            for (int p = 0; p < 4; p++) {
                uint32_t row = (uint32_t)(wn * 64 + p * 16 + lml);
                LDSM4(bf[p][0], bf[p][1], bf[p][2], bf[p][3],
                      sbuf + 16384u + row * 128 +
                      (uint32_t)((ck ^ (row & 7)) << 4));
            }
            #pragma unroll
            for (int a = 0; a < 4; a++)
                #pragma unroll
                for (int n = 0; n < 8; n++) {
                    int p = n >> 1, s = n & 1;
                    MMA16816(acc[a][n], af[a], bf[p][s], bf[p][s + 2]);
                }
        }

        if (c + 2 < KITERS) CP_WAIT1();
        else                CP_WAIT0();
        __syncthreads();
    }

    #pragma unroll
    for (int n = 0; n < 8; n++) {
        const int col = n0 + wn * 64 + n * 8 + (lane & 3) * 2;
        const float2 bb = *(const float2*)&b2[col];
        #pragma unroll
        for (int a = 0; a < 4; a++) {
            const size_t r0 = (size_t)m0 + wm * 64 + a * 16 + (lane >> 2);
            float2 o0 = { acc[a][n][0] + bb.x, acc[a][n][1] + bb.y };
            float2 o1 = { acc[a][n][2] + bb.x, acc[a][n][3] + bb.y };
            *(float2*)&out[r0 * VV + col]       = o0;
            *(float2*)&out[(r0 + 8) * VV + col] = o1;
        }
    }
}

// ---------------------------------------------------------------------------
// Launch
// ---------------------------------------------------------------------------
extern "C" void kernel_launch(void* const* d_in, const int* in_sizes, int n_in,
                              void* d_out, int out_size)
{
    const float* enc = (const float*)d_in[0];
    const float* dec = (const float*)d_in[1];
    const float* W1  = (const float*)d_in[2];
    const float* b1  = (const float*)d_in[3];
    const float* W2  = (const float*)d_in[4];
    const float* b2  = (const float*)d_in[5];
    float* out = (float*)d_out;

    float *pe = nullptr, *pd = nullptr;
    __half *ga = nullptr, *gb = nullptr;
    cudaGetSymbolAddress((void**)&pe, g_proj_e);
    cudaGetSymbolAddress((void**)&pd, g_proj_d);
    cudaGetSymbolAddress((void**)&ga, g_A);
    cudaGetSymbolAddress((void**)&gb, g_B);

    cudaFuncSetAttribute(joint_gemm,
                         cudaFuncAttributeMaxDynamicSharedMemorySize, SMEM_TOTAL);

    proj_both<<<dim3(HH / 32, 15), 128>>>(enc, dec, W1, b1, pe, pd);
    prep_w2<<<dim3(VV / 32, HH / 32), 256>>>(W2, gb);
    prep_a<<<dim3(U_, T_, B_), 160>>>(ga);

    joint_gemm<<<dim3(VV / BN, MTOT / BM), 128, SMEM_TOTAL>>>(ga, gb, b2, out);
}